// round 12
// baseline (speedup 1.0000x reference)
#include <cuda_runtime.h>
#include <cuda_bf16.h>

// Upsample2d (up=2, binomial 4-tap) == separable interp:
//   out[2m]   = 0.25*x[m-1] + 0.75*x[m]
//   out[2m+1] = 0.75*x[m]   + 0.25*x[m+1]
// R12: persistent warps + cross-task software pipelining. Task = (img, 4-row
// strip); warp issues the NEXT task's 5 LDG.128s before computing/storing the
// current task, hiding the L2 prologue behind 9 STG.256 + FMA work. Only the
// first task per warp pays exposed latency (3552 vs 16384 exposures).

#define W_IN  128
#define H_IN  128
#define W_OUT 256
#define H_OUT 256
#define WARPS   8
#define RPW     4                         // input rows per task
#define NBLOCKS 444                       // 3 per SM x 148 SMs, single wave
#define NWARPSG (NBLOCKS * WARPS)         // 3552 warps
#define NTASKS  (1024 * (H_IN / RPW))     // 32768 tasks

__device__ __forceinline__ void compute_h(float4 a, int lane, float* __restrict__ h) {
    float left  = __shfl_up_sync(0xffffffffu, a.w, 1);
    float right = __shfl_down_sync(0xffffffffu, a.x, 1);
    if (lane == 0)  left  = 0.0f;
    if (lane == 31) right = 0.0f;
    h[0] = 0.25f * left + 0.75f * a.x;
    h[1] = 0.75f * a.x  + 0.25f * a.y;
    h[2] = 0.25f * a.x  + 0.75f * a.y;
    h[3] = 0.75f * a.y  + 0.25f * a.z;
    h[4] = 0.25f * a.y  + 0.75f * a.z;
    h[5] = 0.75f * a.z  + 0.25f * a.w;
    h[6] = 0.25f * a.z  + 0.75f * a.w;
    h[7] = 0.75f * a.w  + 0.25f * right;
}

__device__ __forceinline__ void store_row_v8(float* p,
                                             const float* __restrict__ w0,
                                             const float* __restrict__ w1,
                                             float c0, float c1) {
    float o0 = c0 * w0[0] + c1 * w1[0];
    float o1 = c0 * w0[1] + c1 * w1[1];
    float o2 = c0 * w0[2] + c1 * w1[2];
    float o3 = c0 * w0[3] + c1 * w1[3];
    float o4 = c0 * w0[4] + c1 * w1[4];
    float o5 = c0 * w0[5] + c1 * w1[5];
    float o6 = c0 * w0[6] + c1 * w1[6];
    float o7 = c0 * w0[7] + c1 * w1[7];
    asm volatile("st.global.cs.v8.f32 [%0], {%1,%2,%3,%4,%5,%6,%7,%8};"
                 :: "l"(p), "f"(o0), "f"(o1), "f"(o2), "f"(o3),
                    "f"(o4), "f"(o5), "f"(o6), "f"(o7)
                 : "memory");
}

// Issue the 5 front-batched LDG.128s for task t (halo row clamped).
__device__ __forceinline__ void load_task(const float* __restrict__ x,
                                          int t, int c0,
                                          float4* __restrict__ v) {
    const int img   = t >> 5;                 // 32 strips per image
    const int strip = t & 31;
    const int r0    = strip * RPW;
    const float* xi = x + (size_t)img * (H_IN * W_IN);
    const int rh = (r0 == 0) ? 0 : (r0 - 1);
    v[0] = *reinterpret_cast<const float4*>(xi + rh * W_IN + c0);
    #pragma unroll
    for (int k = 0; k < RPW; ++k)
        v[k + 1] = *reinterpret_cast<const float4*>(xi + (r0 + k) * W_IN + c0);
}

// Compute + store task t from its 5 preloaded rows.
__device__ __forceinline__ void process_task(float* __restrict__ out,
                                             int t, int lane, int oc,
                                             const float4* __restrict__ v) {
    const int img   = t >> 5;
    const int strip = t & 31;
    const int r0    = strip * RPW;
    float* oi = out + (size_t)img * (H_OUT * W_OUT);

    float hp[8];
    if (r0 == 0) {
        #pragma unroll
        for (int j = 0; j < 8; ++j) hp[j] = 0.0f;
    } else {
        compute_h(v[0], lane, hp);
    }

    #pragma unroll
    for (int k = 0; k < RPW; ++k) {
        const int n = r0 + k;
        float h[8];
        compute_h(v[k + 1], lane, h);
        if (n > 0)
            store_row_v8(oi + (2 * n - 1) * W_OUT + oc, hp, h, 0.75f, 0.25f);
        store_row_v8(oi + (2 * n) * W_OUT + oc, hp, h, 0.25f, 0.75f);
        #pragma unroll
        for (int j = 0; j < 8; ++j) hp[j] = h[j];
    }

    if (r0 + RPW == H_IN) {
        float z[8] = {0, 0, 0, 0, 0, 0, 0, 0};
        store_row_v8(oi + (H_OUT - 1) * W_OUT + oc, hp, z, 0.75f, 0.0f);
    }
}

__global__ __launch_bounds__(WARPS * 32, 3)
void Upsample_63797444215162_kernel(const float* __restrict__ x,
                                    float* __restrict__ out) {
    const int tid  = threadIdx.x;
    const int warp = tid >> 5;
    const int lane = tid & 31;
    const int c0   = lane * 4;
    const int oc   = lane * 8;
    const int g    = blockIdx.x * WARPS + warp;   // global warp id

    float4 va[RPW + 1], vb[RPW + 1];

    int t = g;
    if (t >= NTASKS) return;
    load_task(x, t, c0, va);

    while (true) {
        // current task in va
        int tn = t + NWARPSG;
        if (tn < NTASKS) load_task(x, tn, c0, vb);   // prefetch next
        process_task(out, t, lane, oc, va);
        if (tn >= NTASKS) break;
        t = tn;

        // current task in vb
        tn = t + NWARPSG;
        if (tn < NTASKS) load_task(x, tn, c0, va);   // prefetch next
        process_task(out, t, lane, oc, vb);
        if (tn >= NTASKS) break;
        t = tn;
    }
}

extern "C" void kernel_launch(void* const* d_in, const int* in_sizes, int n_in,
                              void* d_out, int out_size) {
    const float* x = (const float*)d_in[0];   // [8,128,128,128] fp32
    // d_in[1] is the fixed 4x4 binomial kernel; weights folded into code.
    float* out = (float*)d_out;               // [8,128,256,256] fp32

    Upsample_63797444215162_kernel<<<NBLOCKS, WARPS * 32>>>(x, out);
}

// round 13
// speedup vs baseline: 1.2155x; 1.2155x over previous
#include <cuda_runtime.h>
#include <cuda_bf16.h>

// Upsample2d (up=2, binomial 4-tap) == separable interp:
//   out[2m]   = 0.25*x[m-1] + 0.75*x[m]
//   out[2m+1] = 0.75*x[m]   + 0.25*x[m+1]
// R13: R11 (RPW=8 front-batched loads, warp = full input row, v8 .cs stores,
// grid 2048) with the per-store compiler barrier removed (no "memory"
// clobber) and all 18 SHFL halo exchanges pre-issued before the store loop,
// so shuffle latency pipelines instead of serializing per iteration.

#define W_IN  128
#define H_IN  128
#define W_OUT 256
#define H_OUT 256
#define WARPS 8
#define RPW   8      // input rows per warp strip
// block covers WARPS*RPW = 64 input rows -> 2 blocks per image

// h from row data + precomputed (already edge-masked) neighbors
__device__ __forceinline__ void compute_h_pre(float4 a, float left, float right,
                                              float* __restrict__ h) {
    h[0] = 0.25f * left + 0.75f * a.x;
    h[1] = 0.75f * a.x  + 0.25f * a.y;
    h[2] = 0.25f * a.x  + 0.75f * a.y;
    h[3] = 0.75f * a.y  + 0.25f * a.z;
    h[4] = 0.25f * a.y  + 0.75f * a.z;
    h[5] = 0.75f * a.z  + 0.25f * a.w;
    h[6] = 0.25f * a.z  + 0.75f * a.w;
    h[7] = 0.75f * a.w  + 0.25f * right;
}

// NOTE: volatile (not removable) but NO memory clobber — values arrive via
// registers; no other code reads the output, so no ordering is required.
// Keeping the clobber out lets ptxas interleave FMAs/SHFLs across stores.
__device__ __forceinline__ void store_row_v8(float* p,
                                             const float* __restrict__ w0,
                                             const float* __restrict__ w1,
                                             float c0, float c1) {
    float o0 = c0 * w0[0] + c1 * w1[0];
    float o1 = c0 * w0[1] + c1 * w1[1];
    float o2 = c0 * w0[2] + c1 * w1[2];
    float o3 = c0 * w0[3] + c1 * w1[3];
    float o4 = c0 * w0[4] + c1 * w1[4];
    float o5 = c0 * w0[5] + c1 * w1[5];
    float o6 = c0 * w0[6] + c1 * w1[6];
    float o7 = c0 * w0[7] + c1 * w1[7];
    asm volatile("st.global.cs.v8.f32 [%0], {%1,%2,%3,%4,%5,%6,%7,%8};"
                 :: "l"(p), "f"(o0), "f"(o1), "f"(o2), "f"(o3),
                    "f"(o4), "f"(o5), "f"(o6), "f"(o7));
}

__global__ __launch_bounds__(WARPS * 32)
void Upsample_63797444215162_kernel(const float* __restrict__ x,
                                    float* __restrict__ out) {
    const int tid  = threadIdx.x;
    const int warp = tid >> 5;
    const int lane = tid & 31;
    const int img  = blockIdx.x >> 1;           // 2 blocks per image
    const int half = blockIdx.x & 1;

    const float* __restrict__ xi = x   + (size_t)img * (H_IN * W_IN);
    float*       __restrict__ oi = out + (size_t)img * (H_OUT * W_OUT);

    const int r0 = half * (WARPS * RPW) + warp * RPW;   // strip start row
    const int c0 = lane * 4;                            // input col base
    const int oc = lane * 8;                            // output col base

    // ---- Front-batched loads: halo row (clamped) + 8 body rows ----
    const int rh = (r0 == 0) ? 0 : (r0 - 1);
    float4 v[RPW + 1];
    v[0] = *reinterpret_cast<const float4*>(xi + rh * W_IN + c0);
    #pragma unroll
    for (int k = 0; k < RPW; ++k)
        v[k + 1] = *reinterpret_cast<const float4*>(xi + (r0 + k) * W_IN + c0);

    // ---- Pre-issue all halo shuffles (pipelined at issue rate) ----
    float lft[RPW + 1], rgt[RPW + 1];
    #pragma unroll
    for (int r = 0; r < RPW + 1; ++r) {
        lft[r] = __shfl_up_sync(0xffffffffu, v[r].w, 1);
        rgt[r] = __shfl_down_sync(0xffffffffu, v[r].x, 1);
    }
    if (lane == 0) {
        #pragma unroll
        for (int r = 0; r < RPW + 1; ++r) lft[r] = 0.0f;
    }
    if (lane == 31) {
        #pragma unroll
        for (int r = 0; r < RPW + 1; ++r) rgt[r] = 0.0f;
    }

    // ---- Rolling vertical combine + stores (pure FMA + STG, no barriers) ----
    float hp[8];
    if (r0 == 0) {
        #pragma unroll
        for (int j = 0; j < 8; ++j) hp[j] = 0.0f;
    } else {
        compute_h_pre(v[0], lft[0], rgt[0], hp);
    }

    #pragma unroll
    for (int k = 0; k < RPW; ++k) {
        const int n = r0 + k;
        float h[8];
        compute_h_pre(v[k + 1], lft[k + 1], rgt[k + 1], h);

        // out row 2n-1 = 0.75*h(n-1) + 0.25*h(n)   (row -1 doesn't exist)
        if (n > 0)
            store_row_v8(oi + (2 * n - 1) * W_OUT + oc, hp, h, 0.75f, 0.25f);
        // out row 2n   = 0.25*h(n-1) + 0.75*h(n)
        store_row_v8(oi + (2 * n) * W_OUT + oc, hp, h, 0.25f, 0.75f);

        #pragma unroll
        for (int j = 0; j < 8; ++j) hp[j] = h[j];
    }

    // last output row 2H-1 = 0.75*h(H-1), owned by the last strip
    if (r0 + RPW == H_IN) {
        float z[8] = {0, 0, 0, 0, 0, 0, 0, 0};
        store_row_v8(oi + (H_OUT - 1) * W_OUT + oc, hp, z, 0.75f, 0.0f);
    }
}

extern "C" void kernel_launch(void* const* d_in, const int* in_sizes, int n_in,
                              void* d_out, int out_size) {
    const float* x = (const float*)d_in[0];   // [8,128,128,128] fp32
    // d_in[1] is the fixed 4x4 binomial kernel; weights folded into code.
    float* out = (float*)d_out;               // [8,128,256,256] fp32

    const int n_img = in_sizes[0] / (H_IN * W_IN);   // B*C = 1024
    Upsample_63797444215162_kernel<<<n_img * 2, WARPS * 32>>>(x, out);
}